// round 6
// baseline (speedup 1.0000x reference)
#include <cuda_runtime.h>
#include <cstdint>
#include <cstddef>

// ============================================================================
// StackedLoRALinear on GB300 — family-target build (no tcgen05). R5 showed we
// sit at the fallback-HMMA tf32 floor (~512 FLOP/cyc/SM). Switch engine to
// int8 mma.m16n8k32 with two-limb base-256 row quantization:
//   Q = 256*qh + ql (qh,ql s8), dot = 65536*hh + 256*(h*l + l*h)  [ll dropped]
// -> 3 IMMA per k32 vs 4 tf32-HMMA per k32 = 0.75x tensor instructions.
// LoRA fused via augmented K (last 4 k-tiles read z/Bp with scale-ratio fold).
// ============================================================================

#define DEV __device__ __forceinline__

static constexpr int D_DIM  = 3072;
static constexpr int M_ROWS = 16384;    // 4 * 4096
static constexpr int R_DIM  = 128;      // depth * rank

static constexpr int BM = 128, BN = 128, BK = 32;
static constexpr int STAGES = 4;
static constexpr int SROW   = 48;              // smem bytes/row: 32 data + 16 pad
static constexpr int PLANE  = 128 * SROW;      // 6144 B  (Ah | Al | Bh | Bl)
static constexpr int STAGE_B = 4 * PLANE;      // 24576 B
static constexpr int SMEM_B  = STAGES * STAGE_B; // 98304 B

// ---------------- scratch (static device globals; no allocation) ------------
__device__ __align__(16) int8_t g_xh[(size_t)M_ROWS * D_DIM];
__device__ __align__(16) int8_t g_xl[(size_t)M_ROWS * D_DIM];
__device__ __align__(16) int8_t g_Wh[(size_t)D_DIM * D_DIM];
__device__ __align__(16) int8_t g_Wl[(size_t)D_DIM * D_DIM];
__device__ __align__(16) int8_t g_Ah[R_DIM * D_DIM];
__device__ __align__(16) int8_t g_Al[R_DIM * D_DIM];
__device__ __align__(16) int8_t g_Bph[D_DIM * R_DIM];
__device__ __align__(16) int8_t g_Bpl[D_DIM * R_DIM];
__device__ __align__(16) int8_t g_zh[(size_t)M_ROWS * R_DIM];
__device__ __align__(16) int8_t g_zl[(size_t)M_ROWS * R_DIM];
__device__ float g_z[(size_t)M_ROWS * R_DIM];
__device__ float g_sx[M_ROWS], g_sw[D_DIM], g_sa[R_DIM], g_sb[D_DIM], g_sz[M_ROWS];

// ---------------- helpers ----------------------------------------------------
DEV uint32_t smem_u32(const void* p) {
    uint32_t a;
    asm("{ .reg .u64 t; cvta.to.shared.u64 t, %1; cvt.u32.u64 %0, t; }"
        : "=r"(a) : "l"(p));
    return a;
}

DEV void cp16(uint32_t s, const void* g) {
    asm volatile("cp.async.cg.shared.global [%0], [%1], 16;\n" :: "r"(s), "l"(g));
}

DEV void imma_f(int d[4], uint32_t a0, uint32_t a1, uint32_t a2, uint32_t a3,
                uint32_t b0, uint32_t b1) {            // D = A*B + 0
    asm volatile(
        "mma.sync.aligned.m16n8k32.row.col.s32.s8.s8.s32 "
        "{%0,%1,%2,%3},{%4,%5,%6,%7},{%8,%9},{%10,%11,%12,%13};"
        : "=r"(d[0]), "=r"(d[1]), "=r"(d[2]), "=r"(d[3])
        : "r"(a0), "r"(a1), "r"(a2), "r"(a3), "r"(b0), "r"(b1),
          "r"(0), "r"(0), "r"(0), "r"(0));
}
DEV void imma_a(int d[4], uint32_t a0, uint32_t a1, uint32_t a2, uint32_t a3,
                uint32_t b0, uint32_t b1) {            // D += A*B
    asm volatile(
        "mma.sync.aligned.m16n8k32.row.col.s32.s8.s8.s32 "
        "{%0,%1,%2,%3},{%4,%5,%6,%7},{%8,%9},{%0,%1,%2,%3};"
        : "+r"(d[0]), "+r"(d[1]), "+r"(d[2]), "+r"(d[3])
        : "r"(a0), "r"(a1), "r"(a2), "r"(a3), "r"(b0), "r"(b1));
}

// ---------------- quantization: per-row, two s8 limbs, base 256 -------------
// Q = rn(v * 32512 / rowmax); qh = round(Q/256) in s8; ql = Q - 256*qh in s8.
template<int C, int TPB>
__global__ void quant_rows(const float* __restrict__ src,
                           int8_t* __restrict__ qh, int8_t* __restrict__ ql,
                           float* __restrict__ scale) {
    constexpr int VPT = C / TPB;
    __shared__ float red[TPB / 32];
    const int row = blockIdx.x, tid = threadIdx.x;
    const float* s = src + (size_t)row * C;
    float v[VPT]; float mx = 0.f;
    #pragma unroll
    for (int i = 0; i < VPT; ++i) { v[i] = s[i * TPB + tid]; mx = fmaxf(mx, fabsf(v[i])); }
    #pragma unroll
    for (int o = 16; o; o >>= 1) mx = fmaxf(mx, __shfl_xor_sync(~0u, mx, o));
    if ((tid & 31) == 0) red[tid >> 5] = mx;
    __syncthreads();
    mx = red[0];
    #pragma unroll
    for (int w = 1; w < TPB / 32; ++w) mx = fmaxf(mx, red[w]);
    mx = fmaxf(mx, 1e-30f);
    const float s2q = 32512.f / mx;
    #pragma unroll
    for (int i = 0; i < VPT; ++i) {
        int Q = __float2int_rn(v[i] * s2q);
        int h = (Q + 128) >> 8;
        int l = Q - (h << 8);
        qh[(size_t)row * C + i * TPB + tid] = (int8_t)h;
        ql[(size_t)row * C + i * TPB + tid] = (int8_t)l;
    }
    if (tid == 0) scale[row] = mx / 32512.f;
}

// Bp[n][j] = lora_B[d][n][r], j = d*32+r; quantize per n-row (C=128).
__global__ void quant_Bp(const float* __restrict__ lB,
                         int8_t* __restrict__ qh, int8_t* __restrict__ ql,
                         float* __restrict__ scale) {
    __shared__ float red[4];
    const int n = blockIdx.x, j = threadIdx.x;
    float v = lB[(size_t)((j >> 5) * D_DIM + n) * 32 + (j & 31)];
    float mx = fabsf(v);
    #pragma unroll
    for (int o = 16; o; o >>= 1) mx = fmaxf(mx, __shfl_xor_sync(~0u, mx, o));
    if ((j & 31) == 0) red[j >> 5] = mx;
    __syncthreads();
    mx = fmaxf(fmaxf(red[0], red[1]), fmaxf(red[2], red[3]));
    mx = fmaxf(mx, 1e-30f);
    int Q = __float2int_rn(v * (32512.f / mx));
    int h = (Q + 128) >> 8, l = Q - (h << 8);
    qh[(size_t)n * R_DIM + j] = (int8_t)h;
    ql[(size_t)n * R_DIM + j] = (int8_t)l;
    if (j == 0) scale[n] = mx / 32512.f;
}

// ---------------- int8 dual-source GEMM --------------------------------------
// C[m][n] = sA1[m]*sB1[n]*dot1 + sA2[m]*sB2[n]*dot2 + bias[n]
// via one augmented-K loop; K2 tiles fold with ratio rm*rn into the same facc.
// CTA 128x128, 8 warps (2M x 4N), warp tile 64x32, BK=32, 4-stage cp.async.
__global__ void __launch_bounds__(256, 1)
gemm_i8(const int8_t* __restrict__ A1h, const int8_t* __restrict__ A1l, int lda1,
        const int8_t* __restrict__ B1h, const int8_t* __restrict__ B1l, int ldb1, int K1,
        const int8_t* __restrict__ A2h, const int8_t* __restrict__ A2l, int lda2,
        const int8_t* __restrict__ B2h, const int8_t* __restrict__ B2l, int ldb2, int K2,
        const float* __restrict__ sA1, const float* __restrict__ sB1,
        const float* __restrict__ sA2, const float* __restrict__ sB2,
        const float* __restrict__ bias, float* __restrict__ C, int ldc)
{
    extern __shared__ __align__(16) char smem[];
    const uint32_t sbase = smem_u32(smem);
    const int tid  = threadIdx.x;
    const int wid  = tid >> 5, lane = tid & 31;
    const int g    = lane >> 2, t = lane & 3;
    const int wm   = (wid & 1) * 64, wn = (wid >> 1) * 32;
    const int mBase = blockIdx.y * BM, nBase = blockIdx.x * BN;
    const int NT1 = K1 / BK, NT = (K1 + K2) / BK;
    const int rhalf = tid >> 1, chalf = tid & 1;     // loader: 2 x 16B per row

    float facc[4][4][4];
    #pragma unroll
    for (int mi = 0; mi < 4; ++mi)
        #pragma unroll
        for (int ni = 0; ni < 4; ++ni)
            #pragma unroll
            for (int c = 0; c < 4; ++c) facc[mi][ni][c] = 0.f;

    auto load_tile = [&](int kt) {
        if (kt < NT) {
            const int8_t *Ah, *Al, *Bh, *Bl; int lda, ldb, kOff;
            if (kt < NT1) { Ah = A1h; Al = A1l; Bh = B1h; Bl = B1l;
                            lda = lda1; ldb = ldb1; kOff = kt * BK; }
            else          { Ah = A2h; Al = A2l; Bh = B2h; Bl = B2l;
                            lda = lda2; ldb = ldb2; kOff = kt * BK - K1; }
            const uint32_t st = sbase + (uint32_t)((kt % STAGES) * STAGE_B);
            const uint32_t so = (uint32_t)(rhalf * SROW + chalf * 16);
            const size_t  ga = (size_t)(mBase + rhalf) * lda + kOff + chalf * 16;
            const size_t  gb = (size_t)(nBase + rhalf) * ldb + kOff + chalf * 16;
            cp16(st + 0 * PLANE + so, Ah + ga);
            cp16(st + 1 * PLANE + so, Al + ga);
            cp16(st + 2 * PLANE + so, Bh + gb);
            cp16(st + 3 * PLANE + so, Bl + gb);
        }
        asm volatile("cp.async.commit_group;\n" ::: "memory");
    };

    for (int s = 0; s < STAGES - 1; ++s) load_tile(s);

    // scale ratios for the K2 (LoRA) tiles
    float rm[8], rn[8];
    if (K2 > 0) {
        #pragma unroll
        for (int j = 0; j < 8; ++j) {
            const int m = mBase + wm + g + 8 * j;
            rm[j] = sA2[m] / sA1[m];
            const int n = nBase + wn + 2 * t + (j >> 1) * 8 + (j & 1);
            rn[j] = sB2[n] / sB1[n];
        }
    }

    for (int kt = 0; kt < NT; ++kt) {
        asm volatile("cp.async.wait_group %0;\n" :: "n"(STAGES - 2) : "memory");
        __syncthreads();
        load_tile(kt + STAGES - 1);

        const char* st = smem + (kt % STAGES) * STAGE_B;

        // fragments  (A: rows m, 32B of k; B: rows n, 32B of k)
        uint32_t aH[4][4], aL[4][4], bH[4][2], bL[4][2];
        #pragma unroll
        for (int mi = 0; mi < 4; ++mi) {
            const char* p = st + (wm + mi * 16 + g) * SROW + 4 * t;
            aH[mi][0] = *(const uint32_t*)(p);
            aH[mi][1] = *(const uint32_t*)(p + 8 * SROW);
            aH[mi][2] = *(const uint32_t*)(p + 16);
            aH[mi][3] = *(const uint32_t*)(p + 8 * SROW + 16);
            aL[mi][0] = *(const uint32_t*)(p + PLANE);
            aL[mi][1] = *(const uint32_t*)(p + PLANE + 8 * SROW);
            aL[mi][2] = *(const uint32_t*)(p + PLANE + 16);
            aL[mi][3] = *(const uint32_t*)(p + PLANE + 8 * SROW + 16);
        }
        #pragma unroll
        for (int ni = 0; ni < 4; ++ni) {
            const char* p = st + 2 * PLANE + (wn + ni * 8 + g) * SROW + 4 * t;
            bH[ni][0] = *(const uint32_t*)(p);
            bH[ni][1] = *(const uint32_t*)(p + 16);
            bL[ni][0] = *(const uint32_t*)(p + PLANE);
            bL[ni][1] = *(const uint32_t*)(p + PLANE + 16);
        }

        const bool isK2 = (kt >= NT1);
        #pragma unroll
        for (int mi = 0; mi < 4; ++mi)
            #pragma unroll
            for (int ni = 0; ni < 4; ++ni) {
                int hh[4], md[4];
                imma_f(hh, aH[mi][0], aH[mi][1], aH[mi][2], aH[mi][3],
                       bH[ni][0], bH[ni][1]);
                imma_f(md, aH[mi][0], aH[mi][1], aH[mi][2], aH[mi][3],
                       bL[ni][0], bL[ni][1]);
                imma_a(md, aL[mi][0], aL[mi][1], aL[mi][2], aL[mi][3],
                       bH[ni][0], bH[ni][1]);
                #pragma unroll
                for (int c = 0; c < 4; ++c) {
                    float tt = fmaf(65536.f, (float)hh[c], 256.f * (float)md[c]);
                    if (isK2) tt *= rm[2 * mi + (c >> 1)] * rn[2 * ni + (c & 1)];
                    facc[mi][ni][c] += tt;
                }
            }
    }

    // -------- epilogue: apply sA1*sB1, add bias, float2 stores --------------
    float s1m[8], s1n[8], bv[8];
    #pragma unroll
    for (int j = 0; j < 8; ++j) {
        s1m[j] = sA1[mBase + wm + g + 8 * j];
        const int n = nBase + wn + 2 * t + (j >> 1) * 8 + (j & 1);
        s1n[j] = sB1[n];
        bv[j]  = bias ? bias[n] : 0.f;
    }
    #pragma unroll
    for (int mi = 0; mi < 4; ++mi) {
        const int m0 = mBase + wm + mi * 16 + g;
        #pragma unroll
        for (int ni = 0; ni < 4; ++ni) {
            const int n0 = nBase + wn + ni * 8 + 2 * t;
            float2 v0, v1;
            v0.x = facc[mi][ni][0] * s1m[2 * mi]     * s1n[2 * ni]     + bv[2 * ni];
            v0.y = facc[mi][ni][1] * s1m[2 * mi]     * s1n[2 * ni + 1] + bv[2 * ni + 1];
            v1.x = facc[mi][ni][2] * s1m[2 * mi + 1] * s1n[2 * ni]     + bv[2 * ni];
            v1.y = facc[mi][ni][3] * s1m[2 * mi + 1] * s1n[2 * ni + 1] + bv[2 * ni + 1];
            *reinterpret_cast<float2*>(C + (size_t)m0 * ldc + n0)       = v0;
            *reinterpret_cast<float2*>(C + (size_t)(m0 + 8) * ldc + n0) = v1;
        }
    }
}

// ---------------- launch -----------------------------------------------------
extern "C" void kernel_launch(void* const* d_in, const int* in_sizes, int n_in,
                              void* d_out, int out_size) {
    const float* x  = (const float*)d_in[0];   // [4,4096,3072]
    const float* W  = (const float*)d_in[1];   // [3072,3072]
    const float* b  = (const float*)d_in[2];   // [3072]
    const float* lA = (const float*)d_in[3];   // [4,32,3072]
    const float* lB = (const float*)d_in[4];   // [4,3072,32]
    float* out = (float*)d_out;                // [4,4096,3072]

    void *xh, *xl, *Wh, *Wl, *Ah, *Al, *Bph, *Bpl, *zh, *zl, *z;
    void *sx, *sw, *sa, *sb, *sz;
    cudaGetSymbolAddress(&xh, g_xh);  cudaGetSymbolAddress(&xl, g_xl);
    cudaGetSymbolAddress(&Wh, g_Wh);  cudaGetSymbolAddress(&Wl, g_Wl);
    cudaGetSymbolAddress(&Ah, g_Ah);  cudaGetSymbolAddress(&Al, g_Al);
    cudaGetSymbolAddress(&Bph, g_Bph); cudaGetSymbolAddress(&Bpl, g_Bpl);
    cudaGetSymbolAddress(&zh, g_zh);  cudaGetSymbolAddress(&zl, g_zl);
    cudaGetSymbolAddress(&z,  g_z);
    cudaGetSymbolAddress(&sx, g_sx);  cudaGetSymbolAddress(&sw, g_sw);
    cudaGetSymbolAddress(&sa, g_sa);  cudaGetSymbolAddress(&sb, g_sb);
    cudaGetSymbolAddress(&sz, g_sz);

    cudaFuncSetAttribute((const void*)gemm_i8,
                         cudaFuncAttributeMaxDynamicSharedMemorySize, SMEM_B);

    // 1) quantize x, W, lora_A (per-row) and packed lora_B (per-n-row)
    quant_rows<D_DIM, 256><<<M_ROWS, 256>>>(x,  (int8_t*)xh, (int8_t*)xl, (float*)sx);
    quant_rows<D_DIM, 256><<<D_DIM,  256>>>(W,  (int8_t*)Wh, (int8_t*)Wl, (float*)sw);
    quant_rows<D_DIM, 256><<<R_DIM,  256>>>(lA, (int8_t*)Ah, (int8_t*)Al, (float*)sa);
    quant_Bp<<<D_DIM, 128>>>(lB, (int8_t*)Bph, (int8_t*)Bpl, (float*)sb);

    // 2) z = x @ Aflat^T   (M=16384, N=128, K=3072; int8 engine, fp32 out)
    gemm_i8<<<dim3(1, M_ROWS / BM), 256, SMEM_B>>>(
        (const int8_t*)xh, (const int8_t*)xl, D_DIM,
        (const int8_t*)Ah, (const int8_t*)Al, D_DIM, D_DIM,
        (const int8_t*)xh, (const int8_t*)xl, D_DIM,
        (const int8_t*)Ah, (const int8_t*)Al, D_DIM, 0,
        (const float*)sx, (const float*)sa, (const float*)sx, (const float*)sa,
        nullptr, (float*)z, R_DIM);

    // 3) quantize z per row (C=128)
    quant_rows<R_DIM, 128><<<M_ROWS, 128>>>((const float*)z,
        (int8_t*)zh, (int8_t*)zl, (float*)sz);

    // 4) out = x@W^T + z@Bp^T + b   (augmented K = 3072 + 128)
    gemm_i8<<<dim3(D_DIM / BN, M_ROWS / BM), 256, SMEM_B>>>(
        (const int8_t*)xh, (const int8_t*)xl, D_DIM,
        (const int8_t*)Wh, (const int8_t*)Wl, D_DIM, D_DIM,
        (const int8_t*)zh, (const int8_t*)zl, R_DIM,
        (const int8_t*)Bph, (const int8_t*)Bpl, R_DIM, R_DIM,
        (const float*)sx, (const float*)sw, (const float*)sz, (const float*)sb,
        b, out, D_DIM);
}

// round 7
// speedup vs baseline: 4.5694x; 4.5694x over previous
#include <cuda_runtime.h>
#include <cuda_fp16.h>
#include <cstdint>
#include <cstddef>

// ============================================================================
// StackedLoRALinear on GB300 — family-target build (no tcgen05).
// R5: tf32 m16n8k8 hit the fallback-HMMA floor (~512 FLOP/cyc/SM, 2554us).
// R6: int8 two-limb IMMA regressed 3x (de-rated IMMA + I2F fold). Reverted.
// R7: fp16 m16n8k16 — same 11-bit mantissa as tf32, but K=16 per instruction
//     at the same HMMA issue rate -> predicted ~2x over R5. No limbs/scales.
//   out[m][n] = b[n] + sum_{k<3072} x[m,k]*W[n,k] + sum_{j<128} z[m,j]*Bp[n,j]
//   z[m][j]   = sum_k x[m,k]*Aflat[j,k]    (augmented-K fusion, fp32 accum)
// ============================================================================

#define DEV __device__ __forceinline__

static constexpr int D_DIM  = 3072;
static constexpr int M_ROWS = 16384;     // 4 * 4096
static constexpr int R_DIM  = 128;       // depth * rank

static constexpr int BM = 128, BN = 128, BK = 64;
static constexpr int STAGES = 3;
static constexpr int SROWH  = 72;                   // smem halves/row: 64 + 8 pad
static constexpr int ROW_B  = SROWH * 2;            // 144 B (conflict-free, = R5)
static constexpr int PLANE  = BM * ROW_B;           // 18432 B (A plane; B same)
static constexpr int STAGE_B = 2 * PLANE;           // 36864 B
static constexpr int SMEM_B  = STAGES * STAGE_B;    // 110592 B

// ---------------- scratch (static device globals; no allocation) ------------
__device__ __align__(16) __half g_xh [(size_t)M_ROWS * D_DIM];  // 100.7 MB
__device__ __align__(16) __half g_Wh [(size_t)D_DIM * D_DIM];   // 18.9 MB
__device__ __align__(16) __half g_Ah [R_DIM * D_DIM];           // 0.75 MB
__device__ __align__(16) __half g_Bph[D_DIM * R_DIM];           // 0.75 MB
__device__ __align__(16) __half g_zh [(size_t)M_ROWS * R_DIM];  // 4 MB

// ---------------- helpers ----------------------------------------------------
DEV uint32_t smem_u32(const void* p) {
    uint32_t a;
    asm("{ .reg .u64 t; cvta.to.shared.u64 t, %1; cvt.u32.u64 %0, t; }"
        : "=r"(a) : "l"(p));
    return a;
}

DEV void cp16(uint32_t s, const void* g) {
    asm volatile("cp.async.cg.shared.global [%0], [%1], 16;\n" :: "r"(s), "l"(g));
}

DEV void mma16816(float c[4],
                  uint32_t a0, uint32_t a1, uint32_t a2, uint32_t a3,
                  uint32_t b0, uint32_t b1) {
    asm volatile(
        "mma.sync.aligned.m16n8k16.row.col.f32.f16.f16.f32 "
        "{%0,%1,%2,%3},{%4,%5,%6,%7},{%8,%9},{%0,%1,%2,%3};"
        : "+f"(c[0]), "+f"(c[1]), "+f"(c[2]), "+f"(c[3])
        : "r"(a0), "r"(a1), "r"(a2), "r"(a3), "r"(b0), "r"(b1));
}

// ---------------- prep: fp32 -> fp16 (rn) + pack lora_B ---------------------
__global__ void prep_kernel(const float* __restrict__ x,
                            const float* __restrict__ W,
                            const float* __restrict__ lA,
                            const float* __restrict__ lB) {
    const size_t stride = (size_t)gridDim.x * blockDim.x;
    const size_t g0 = (size_t)blockIdx.x * blockDim.x + threadIdx.x;
    // x: 50.33M elems, 2 per thread-step via float2 -> half2
    for (size_t i = g0; i < (size_t)M_ROWS * D_DIM / 2; i += stride) {
        float2 v = reinterpret_cast<const float2*>(x)[i];
        reinterpret_cast<__half2*>(g_xh)[i] = __floats2half2_rn(v.x, v.y);
    }
    for (size_t i = g0; i < (size_t)D_DIM * D_DIM / 2; i += stride) {
        float2 v = reinterpret_cast<const float2*>(W)[i];
        reinterpret_cast<__half2*>(g_Wh)[i] = __floats2half2_rn(v.x, v.y);
    }
    for (size_t i = g0; i < (size_t)R_DIM * D_DIM / 2; i += stride) {
        float2 v = reinterpret_cast<const float2*>(lA)[i];
        reinterpret_cast<__half2*>(g_Ah)[i] = __floats2half2_rn(v.x, v.y);
    }
    // Bp[n][j] = lora_B[d][n][r], j = d*32 + r
    for (size_t i = g0; i < (size_t)D_DIM * R_DIM; i += stride) {
        int n = (int)(i >> 7), j = (int)(i & 127);
        int d = j >> 5, r = j & 31;
        g_Bph[i] = __float2half_rn(lB[(size_t)(d * D_DIM + n) * 32 + r]);
    }
}

// ---------------- fp16 dual-K-source GEMM, fp32 accum ------------------------
// C[m][n] = bias[n] + sum_{K1} A1[m,k]*B1[n,k] + sum_{K2} A2[m,k]*B2[n,k]
// CTA 128x128, 8 warps (2M x 4N), warp tile 64x32, BK=64, 3-stage cp.async.
template<bool OUTH>
__global__ void __launch_bounds__(256, 1)
gemm_f16(const __half* __restrict__ A1, int lda1,
         const __half* __restrict__ B1, int ldb1, int K1,
         const __half* __restrict__ A2, int lda2,
         const __half* __restrict__ B2, int ldb2, int K2,
         const float* __restrict__ bias, void* __restrict__ Cout, int ldc)
{
    extern __shared__ __align__(16) char smem[];
    const uint32_t sbase = smem_u32(smem);
    const int tid  = threadIdx.x;
    const int wid  = tid >> 5, lane = tid & 31;
    const int g    = lane >> 2, t = lane & 3;
    const int wm   = (wid & 1) * 64, wn = (wid >> 1) * 32;
    const int mBase = blockIdx.y * BM, nBase = blockIdx.x * BN;
    const int NT1 = K1 / BK, NT = (K1 + K2) / BK;
    const int lrow = tid >> 1;                 // loader: 2 threads/row
    const int lcol = (tid & 1) * 4;            // each does 4 chunks of 16B

    float acc[4][4][4];
    #pragma unroll
    for (int mi = 0; mi < 4; ++mi)
        #pragma unroll
        for (int ni = 0; ni < 4; ++ni)
            #pragma unroll
            for (int c = 0; c < 4; ++c) acc[mi][ni][c] = 0.f;

    auto load_tile = [&](int kt) {
        if (kt < NT) {
            const __half *Ap, *Bq; int lda, ldb, kOff;
            if (kt < NT1) { Ap = A1; Bq = B1; lda = lda1; ldb = ldb1; kOff = kt * BK; }
            else          { Ap = A2; Bq = B2; lda = lda2; ldb = ldb2; kOff = kt * BK - K1; }
            const uint32_t st = sbase + (uint32_t)((kt % STAGES) * STAGE_B);
            const uint32_t so = (uint32_t)(lrow * ROW_B + lcol * 16);
            const __half* ga = Ap + (size_t)(mBase + lrow) * lda + kOff + lcol * 8;
            const __half* gb = Bq + (size_t)(nBase + lrow) * ldb + kOff + lcol * 8;
            #pragma unroll
            for (int c = 0; c < 4; ++c) {
                cp16(st + so + c * 16,         ga + c * 8);
                cp16(st + PLANE + so + c * 16, gb + c * 8);
            }
        }
        asm volatile("cp.async.commit_group;\n" ::: "memory");
    };

    for (int s = 0; s < STAGES - 1; ++s) load_tile(s);

    for (int kt = 0; kt < NT; ++kt) {
        asm volatile("cp.async.wait_group %0;\n" :: "n"(STAGES - 2) : "memory");
        __syncthreads();
        load_tile(kt + STAGES - 1);

        const __half* As = (const __half*)(smem + (kt % STAGES) * STAGE_B);
        const __half* Bs = (const __half*)(smem + (kt % STAGES) * STAGE_B + PLANE);

        #pragma unroll
        for (int k16 = 0; k16 < BK; k16 += 16) {
            uint32_t a[4][4], b[4][2];
            #pragma unroll
            for (int mi = 0; mi < 4; ++mi) {
                const __half* p = As + (wm + mi * 16 + g) * SROWH + k16 + 2 * t;
                a[mi][0] = *(const uint32_t*)(p);
                a[mi][1] = *(const uint32_t*)(p + 8 * SROWH);
                a[mi][2] = *(const uint32_t*)(p + 8);
                a[mi][3] = *(const uint32_t*)(p + 8 * SROWH + 8);
            }
            #pragma unroll
            for (int ni = 0; ni < 4; ++ni) {
                const __half* q = Bs + (wn + ni * 8 + g) * SROWH + k16 + 2 * t;
                b[ni][0] = *(const uint32_t*)(q);
                b[ni][1] = *(const uint32_t*)(q + 8);
            }
            #pragma unroll
            for (int mi = 0; mi < 4; ++mi)
                #pragma unroll
                for (int ni = 0; ni < 4; ++ni)
                    mma16816(acc[mi][ni],
                             a[mi][0], a[mi][1], a[mi][2], a[mi][3],
                             b[ni][0], b[ni][1]);
        }
    }

    // -------- epilogue -------------------------------------------------------
    #pragma unroll
    for (int mi = 0; mi < 4; ++mi) {
        const int m0 = mBase + wm + mi * 16 + g;
        #pragma unroll
        for (int ni = 0; ni < 4; ++ni) {
            const int n0 = nBase + wn + ni * 8 + 2 * t;
            float bx = 0.f, by = 0.f;
            if (bias) {
                const float2 bv = *reinterpret_cast<const float2*>(bias + n0);
                bx = bv.x; by = bv.y;
            }
            if (OUTH) {
                __half* C = (__half*)Cout;
                *reinterpret_cast<__half2*>(C + (size_t)m0 * ldc + n0) =
                    __floats2half2_rn(acc[mi][ni][0], acc[mi][ni][1]);
                *reinterpret_cast<__half2*>(C + (size_t)(m0 + 8) * ldc + n0) =
                    __floats2half2_rn(acc[mi][ni][2], acc[mi][ni][3]);
            } else {
                float* C = (float*)Cout;
                float2 v0 = { acc[mi][ni][0] + bx, acc[mi][ni][1] + by };
                float2 v1 = { acc[mi][ni][2] + bx, acc[mi][ni][3] + by };
                *reinterpret_cast<float2*>(C + (size_t)m0 * ldc + n0)       = v0;
                *reinterpret_cast<float2*>(C + (size_t)(m0 + 8) * ldc + n0) = v1;
            }
        }
    }
}

// ---------------- launch -----------------------------------------------------
extern "C" void kernel_launch(void* const* d_in, const int* in_sizes, int n_in,
                              void* d_out, int out_size) {
    const float* x  = (const float*)d_in[0];   // [4,4096,3072]
    const float* W  = (const float*)d_in[1];   // [3072,3072]
    const float* b  = (const float*)d_in[2];   // [3072]
    const float* lA = (const float*)d_in[3];   // [4,32,3072]
    const float* lB = (const float*)d_in[4];   // [4,3072,32]
    float* out = (float*)d_out;                // [4,4096,3072]

    void *xh, *Wh, *Ah, *Bph, *zh;
    cudaGetSymbolAddress(&xh,  g_xh);
    cudaGetSymbolAddress(&Wh,  g_Wh);
    cudaGetSymbolAddress(&Ah,  g_Ah);
    cudaGetSymbolAddress(&Bph, g_Bph);
    cudaGetSymbolAddress(&zh,  g_zh);

    cudaFuncSetAttribute((const void*)gemm_f16<false>,
                         cudaFuncAttributeMaxDynamicSharedMemorySize, SMEM_B);
    cudaFuncSetAttribute((const void*)gemm_f16<true>,
                         cudaFuncAttributeMaxDynamicSharedMemorySize, SMEM_B);

    // 1) fp16 conversions + lora_B packing
    prep_kernel<<<2048, 256>>>(x, W, lA, lB);

    // 2) z = x @ Aflat^T  (M=16384, N=128, K=3072), written directly as fp16
    gemm_f16<true><<<dim3(1, M_ROWS / BM), 256, SMEM_B>>>(
        (const __half*)xh, D_DIM, (const __half*)Ah, D_DIM, D_DIM,
        (const __half*)xh, D_DIM, (const __half*)Ah, D_DIM, 0,
        nullptr, zh, R_DIM);

    // 3) out = x@W^T + z@Bp^T + b  (augmented K = 3072 + 128)
    gemm_f16<false><<<dim3(D_DIM / BN, M_ROWS / BM), 256, SMEM_B>>>(
        (const __half*)xh, D_DIM, (const __half*)Wh, D_DIM, D_DIM,
        (const __half*)zh, R_DIM, (const __half*)Bph, R_DIM, R_DIM,
        b, out, D_DIM);
}

// round 11
// speedup vs baseline: 5.5119x; 1.2063x over previous
#include <cuda_runtime.h>
#include <cuda_fp16.h>
#include <cstdint>
#include <cstddef>

// ============================================================================
// StackedLoRALinear on GB300 — family-target build (no tcgen05).
// R5 tf32: 2554us (fallback-HMMA floor @K=8). R6 int8: 3x regression (dead).
// R7 fp16 m16n8k16: 1719us. R8: same engine, cut issue overhead:
//   - ldmatrix.x4 fragment loads (24 LDS.32 -> 6 LDSM.x4 per k16-step)
//   - 2 CTAs/SM (221KB smem total, launch_bounds(256,2)) to hide sync/epilogue
//   out = x@W^T + b + z@Bp^T,  z = x@Aflat^T   (augmented-K fusion, fp32 acc)
// ============================================================================

#define DEV __device__ __forceinline__

static constexpr int D_DIM  = 3072;
static constexpr int M_ROWS = 16384;     // 4 * 4096
static constexpr int R_DIM  = 128;       // depth * rank

static constexpr int BM = 128, BN = 128, BK = 64;
static constexpr int STAGES = 3;
static constexpr int SROWH  = 72;                   // smem halves/row: 64 + 8 pad
static constexpr int ROW_B  = SROWH * 2;            // 144 B (conflict-free)
static constexpr int PLANE  = BM * ROW_B;           // 18432 B
static constexpr int STAGE_B = 2 * PLANE;           // 36864 B
static constexpr int SMEM_B  = STAGES * STAGE_B;    // 110592 B -> 2 CTAs/SM

// ---------------- scratch (static device globals; no allocation) ------------
__device__ __align__(16) __half g_xh [(size_t)M_ROWS * D_DIM];  // 100.7 MB
__device__ __align__(16) __half g_Wh [(size_t)D_DIM * D_DIM];   // 18.9 MB
__device__ __align__(16) __half g_Ah [R_DIM * D_DIM];           // 0.75 MB
__device__ __align__(16) __half g_Bph[D_DIM * R_DIM];           // 0.75 MB
__device__ __align__(16) __half g_zh [(size_t)M_ROWS * R_DIM];  // 4 MB

// ---------------- helpers ----------------------------------------------------
DEV uint32_t smem_u32(const void* p) {
    uint32_t a;
    asm("{ .reg .u64 t; cvta.to.shared.u64 t, %1; cvt.u32.u64 %0, t; }"
        : "=r"(a) : "l"(p));
    return a;
}

DEV void cp16(uint32_t s, const void* g) {
    asm volatile("cp.async.cg.shared.global [%0], [%1], 16;\n" :: "r"(s), "l"(g));
}

DEV void ldsm4(uint32_t& r0, uint32_t& r1, uint32_t& r2, uint32_t& r3,
               uint32_t addr) {
    asm volatile("ldmatrix.sync.aligned.m8n8.x4.shared.b16 {%0,%1,%2,%3}, [%4];"
                 : "=r"(r0), "=r"(r1), "=r"(r2), "=r"(r3) : "r"(addr));
}

DEV void mma16816(float c[4],
                  uint32_t a0, uint32_t a1, uint32_t a2, uint32_t a3,
                  uint32_t b0, uint32_t b1) {
    asm volatile(
        "mma.sync.aligned.m16n8k16.row.col.f32.f16.f16.f32 "
        "{%0,%1,%2,%3},{%4,%5,%6,%7},{%8,%9},{%0,%1,%2,%3};"
        : "+f"(c[0]), "+f"(c[1]), "+f"(c[2]), "+f"(c[3])
        : "r"(a0), "r"(a1), "r"(a2), "r"(a3), "r"(b0), "r"(b1));
}

// ---------------- prep: fp32 -> fp16 (rn) + pack lora_B ---------------------
__global__ void prep_kernel(const float* __restrict__ x,
                            const float* __restrict__ W,
                            const float* __restrict__ lA,
                            const float* __restrict__ lB) {
    const size_t stride = (size_t)gridDim.x * blockDim.x;
    const size_t g0 = (size_t)blockIdx.x * blockDim.x + threadIdx.x;
    for (size_t i = g0; i < (size_t)M_ROWS * D_DIM / 4; i += stride) {
        float4 v = reinterpret_cast<const float4*>(x)[i];
        __half2 h0 = __floats2half2_rn(v.x, v.y);
        __half2 h1 = __floats2half2_rn(v.z, v.w);
        reinterpret_cast<uint2*>(g_xh)[i] =
            make_uint2(*(uint32_t*)&h0, *(uint32_t*)&h1);
    }
    for (size_t i = g0; i < (size_t)D_DIM * D_DIM / 4; i += stride) {
        float4 v = reinterpret_cast<const float4*>(W)[i];
        __half2 h0 = __floats2half2_rn(v.x, v.y);
        __half2 h1 = __floats2half2_rn(v.z, v.w);
        reinterpret_cast<uint2*>(g_Wh)[i] =
            make_uint2(*(uint32_t*)&h0, *(uint32_t*)&h1);
    }
    for (size_t i = g0; i < (size_t)R_DIM * D_DIM / 2; i += stride) {
        float2 v = reinterpret_cast<const float2*>(lA)[i];
        reinterpret_cast<__half2*>(g_Ah)[i] = __floats2half2_rn(v.x, v.y);
    }
    // Bp[n][j] = lora_B[d][n][r], j = d*32 + r
    for (size_t i = g0; i < (size_t)D_DIM * R_DIM; i += stride) {
        int n = (int)(i >> 7), j = (int)(i & 127);
        int d = j >> 5, r = j & 31;
        g_Bph[i] = __float2half_rn(lB[(size_t)(d * D_DIM + n) * 32 + r]);
    }
}

// ---------------- fp16 dual-K-source GEMM, fp32 accum ------------------------
// C[m][n] = bias[n] + sum_{K1} A1[m,k]*B1[n,k] + sum_{K2} A2[m,k]*B2[n,k]
// CTA 128x128, 8 warps (2M x 4N), warp tile 64x32, BK=64, 3-stage cp.async,
// ldmatrix fragment loads, 2 CTAs/SM.
template<bool OUTH>
__global__ void __launch_bounds__(256, 2)
gemm_f16(const __half* __restrict__ A1, int lda1,
         const __half* __restrict__ B1, int ldb1, int K1,
         const __half* __restrict__ A2, int lda2,
         const __half* __restrict__ B2, int ldb2, int K2,
         const float* __restrict__ bias, void* __restrict__ Cout, int ldc)
{
    extern __shared__ __align__(16) char smem[];
    const uint32_t sbase = smem_u32(smem);
    const int tid  = threadIdx.x;
    const int wid  = tid >> 5, lane = tid & 31;
    const int g    = lane >> 2, t = lane & 3;
    const int wm   = (wid & 1) * 64, wn = (wid >> 1) * 32;
    const int mBase = blockIdx.y * BM, nBase = blockIdx.x * BN;
    const int NT1 = K1 / BK, NT = (K1 + K2) / BK;
    const int lrow = tid >> 1;                 // loader: 2 threads/row
    const int lcol = (tid & 1) * 4;            // 4 chunks of 16B each

    // ldmatrix per-lane base offsets (halves):
    //  A (x4): row = lane&15, khalf = lane>>4  -> rows 0..15, k +0/+8
    const uint32_t aRow = (uint32_t)(lane & 15);
    const uint32_t aKof = (uint32_t)((lane >> 4) << 3);
    //  B (x4 over an n-pair): row = (lane>>4)*8 + (lane&7), khalf = (lane>>3)&1
    const uint32_t bRow = (uint32_t)(((lane >> 4) << 3) + (lane & 7));
    const uint32_t bKof = (uint32_t)(((lane >> 3) & 1) << 3);

    float acc[4][4][4];
    #pragma unroll
    for (int mi = 0; mi < 4; ++mi)
        #pragma unroll
        for (int ni = 0; ni < 4; ++ni)
            #pragma unroll
            for (int c = 0; c < 4; ++c) acc[mi][ni][c] = 0.f;

    auto load_tile = [&](int kt) {
        if (kt < NT) {
            const __half *Ap, *Bq; int lda, ldb, kOff;
            if (kt < NT1) { Ap = A1; Bq = B1; lda = lda1; ldb = ldb1; kOff = kt * BK; }
            else          { Ap = A2; Bq = B2; lda = lda2; ldb = ldb2; kOff = kt * BK - K1; }
            const uint32_t st = sbase + (uint32_t)((kt % STAGES) * STAGE_B);
            const uint32_t so = (uint32_t)(lrow * ROW_B + lcol * 16);
            const __half* ga = Ap + (size_t)(mBase + lrow) * lda + kOff + lcol * 8;
            const __half* gb = Bq + (size_t)(nBase + lrow) * ldb + kOff + lcol * 8;
            #pragma unroll
            for (int c = 0; c < 4; ++c) {
                cp16(st + so + c * 16,         ga + c * 8);
                cp16(st + PLANE + so + c * 16, gb + c * 8);
            }
        }
        asm volatile("cp.async.commit_group;\n" ::: "memory");
    };

    for (int s = 0; s < STAGES - 1; ++s) load_tile(s);

    for (int kt = 0; kt < NT; ++kt) {
        asm volatile("cp.async.wait_group %0;\n" :: "n"(STAGES - 2) : "memory");
        __syncthreads();
        load_tile(kt + STAGES - 1);

        const uint32_t stA = sbase + (uint32_t)((kt % STAGES) * STAGE_B);
        const uint32_t stB = stA + (uint32_t)PLANE;

        #pragma unroll
        for (int k16 = 0; k16 < BK; k16 += 16) {
            uint32_t a[4][4], b[4][2];
            #pragma unroll
            for (int mi = 0; mi < 4; ++mi) {
                const uint32_t addr = stA +
                    ((uint32_t)(wm + mi * 16) + aRow) * ROW_B +
                    ((uint32_t)k16 + aKof) * 2;
                ldsm4(a[mi][0], a[mi][1], a[mi][2], a[mi][3], addr);
            }
            #pragma unroll
            for (int np = 0; np < 2; ++np) {          // n-pair: ni = 2np, 2np+1
                const uint32_t addr = stB +
                    ((uint32_t)(wn + np * 16) + bRow) * ROW_B +
                    ((uint32_t)k16 + bKof) * 2;
                ldsm4(b[2 * np][0], b[2 * np][1],
                      b[2 * np + 1][0], b[2 * np + 1][1], addr);
            }
            #pragma unroll
            for (int mi = 0; mi < 4; ++mi)
                #pragma unroll
                for (int ni = 0; ni < 4; ++ni)
                    mma16816(acc[mi][ni],
                             a[mi][0], a[mi][1], a[mi][2], a[mi][3],
                             b[ni][0], b[ni][1]);
        }
    }

    // -------- epilogue -------------------------------------------------------
    #pragma unroll
    for (int mi = 0; mi < 4; ++mi) {
        const int m0 = mBase + wm + mi * 16 + g;
        #pragma unroll
        for (int ni = 0; ni < 4; ++ni) {
            const int n0 = nBase + wn + ni * 8 + 2 * t;
            float bx = 0.f, by = 0.f;
            if (bias) {
                const float2 bv = *reinterpret_cast<const float2*>(bias + n0);
                bx = bv.x; by = bv.y;
            }
            if (OUTH) {
                __half* C = (__half*)Cout;
                *reinterpret_cast<__half2*>(C + (size_t)m0 * ldc + n0) =
                    __floats2half2_rn(acc[mi][ni][0], acc[mi][ni][1]);
                *reinterpret_cast<__half2*>(C + (size_t)(m0 + 8) * ldc + n0) =
                    __floats2half2_rn(acc[mi][ni][2], acc[mi][ni][3]);
            } else {
                float* C = (float*)Cout;
                float2 v0 = { acc[mi][ni][0] + bx, acc[mi][ni][1] + by };
                float2 v1 = { acc[mi][ni][2] + bx, acc[mi][ni][3] + by };
                *reinterpret_cast<float2*>(C + (size_t)m0 * ldc + n0)       = v0;
                *reinterpret_cast<float2*>(C + (size_t)(m0 + 8) * ldc + n0) = v1;
            }
        }
    }
}

// ---------------- launch -----------------------------------------------------
extern "C" void kernel_launch(void* const* d_in, const int* in_sizes, int n_in,
                              void* d_out, int out_size) {
    const float* x  = (const float*)d_in[0];   // [4,4096,3072]
    const float* W  = (const float*)d_in[1];   // [3072,3072]
    const float* b  = (const float*)d_in[2];   // [3072]
    const float* lA = (const float*)d_in[3];   // [4,32,3072]
    const float* lB = (const float*)d_in[4];   // [4,3072,32]
    float* out = (float*)d_out;                // [4,4096,3072]

    void *xh, *Wh, *Ah, *Bph, *zh;
    cudaGetSymbolAddress(&xh,  g_xh);
    cudaGetSymbolAddress(&Wh,  g_Wh);
    cudaGetSymbolAddress(&Ah,  g_Ah);
    cudaGetSymbolAddress(&Bph, g_Bph);
    cudaGetSymbolAddress(&zh,  g_zh);

    cudaFuncSetAttribute((const void*)gemm_f16<false>,
                         cudaFuncAttributeMaxDynamicSharedMemorySize, SMEM_B);
    cudaFuncSetAttribute((const void*)gemm_f16<true>,
                         cudaFuncAttributeMaxDynamicSharedMemorySize, SMEM_B);

    // 1) fp16 conversions + lora_B packing
    prep_kernel<<<4096, 256>>>(x, W, lA, lB);

    // 2) z = x @ Aflat^T  (M=16384, N=128, K=3072), written directly as fp16
    gemm_f16<true><<<dim3(1, M_ROWS / BM), 256, SMEM_B>>>(
        (const __half*)xh, D_DIM, (const __half*)Ah, D_DIM, D_DIM,
        (const __half*)xh, D_DIM, (const __half*)Ah, D_DIM, 0,
        nullptr, zh, R_DIM);

    // 3) out = x@W^T + z@Bp^T + b  (augmented K = 3072 + 128)
    gemm_f16<false><<<dim3(D_DIM / BN, M_ROWS / BM), 256, SMEM_B>>>(
        (const __half*)xh, D_DIM, (const __half*)Wh, D_DIM, D_DIM,
        (const __half*)zh, R_DIM, (const __half*)Bph, R_DIM, R_DIM,
        b, out, D_DIM);
}

// round 12
// speedup vs baseline: 6.0293x; 1.0939x over previous
#include <cuda_runtime.h>
#include <cuda_fp16.h>
#include <cstdint>
#include <cstddef>

// ============================================================================
// StackedLoRALinear on GB300 — family-target build (no tcgen05).
// R5 tf32 2554us -> R7 fp16 m16n8k16 1719us -> R8 ldmatrix+2CTA/SM 1425us.
// R9: fold LoRA into the weight matrix (it's linear!):
//      W' = W + sum_d B_d @ A_d   (3072x3072x128 GEMM, ~12us)
//      out = x @ W'^T + b         (single K=3072 GEMM)
// Kills the z-GEMM, the augmented-K tiles, and W's prep conversion.
// Main GEMM is at the fallback-HMMA issue wall (rt~16/SMSP), so cutting
// instruction count is the only remaining lever.
// ============================================================================

#define DEV __device__ __forceinline__

static constexpr int D_DIM  = 3072;
static constexpr int M_ROWS = 16384;     // 4 * 4096
static constexpr int R_DIM  = 128;       // depth * rank

static constexpr int BM = 128, BN = 128, BK = 64;
static constexpr int STAGES = 3;
static constexpr int SROWH  = 72;                   // smem halves/row: 64 + 8 pad
static constexpr int ROW_B  = SROWH * 2;            // 144 B (conflict-free)
static constexpr int PLANE  = BM * ROW_B;           // 18432 B
static constexpr int STAGE_B = 2 * PLANE;           // 36864 B
static constexpr int SMEM_B  = STAGES * STAGE_B;    // 110592 B -> 2 CTAs/SM

// ---------------- scratch (static device globals; no allocation) ------------
__device__ __align__(16) __half g_xh [(size_t)M_ROWS * D_DIM];  // 100.7 MB
__device__ __align__(16) __half g_Wph[(size_t)D_DIM * D_DIM];   // 18.9 MB (W')
__device__ __align__(16) __half g_AfT[(size_t)D_DIM * R_DIM];   // 0.75 MB A^T
__device__ __align__(16) __half g_Bph[(size_t)D_DIM * R_DIM];   // 0.75 MB

// ---------------- helpers ----------------------------------------------------
DEV uint32_t smem_u32(const void* p) {
    uint32_t a;
    asm("{ .reg .u64 t; cvta.to.shared.u64 t, %1; cvt.u32.u64 %0, t; }"
        : "=r"(a) : "l"(p));
    return a;
}

DEV void cp16(uint32_t s, const void* g) {
    asm volatile("cp.async.cg.shared.global [%0], [%1], 16;\n" :: "r"(s), "l"(g));
}

DEV void ldsm4(uint32_t& r0, uint32_t& r1, uint32_t& r2, uint32_t& r3,
               uint32_t addr) {
    asm volatile("ldmatrix.sync.aligned.m8n8.x4.shared.b16 {%0,%1,%2,%3}, [%4];"
                 : "=r"(r0), "=r"(r1), "=r"(r2), "=r"(r3) : "r"(addr));
}

DEV void mma16816(float c[4],
                  uint32_t a0, uint32_t a1, uint32_t a2, uint32_t a3,
                  uint32_t b0, uint32_t b1) {
    asm volatile(
        "mma.sync.aligned.m16n8k16.row.col.f32.f16.f16.f32 "
        "{%0,%1,%2,%3},{%4,%5,%6,%7},{%8,%9},{%0,%1,%2,%3};"
        : "+f"(c[0]), "+f"(c[1]), "+f"(c[2]), "+f"(c[3])
        : "r"(a0), "r"(a1), "r"(a2), "r"(a3), "r"(b0), "r"(b1));
}

// ---------------- prep: x -> fp16; pack A^T and Bp as fp16 ------------------
__global__ void prep_kernel(const float* __restrict__ x,
                            const float* __restrict__ lA,
                            const float* __restrict__ lB) {
    const size_t stride = (size_t)gridDim.x * blockDim.x;
    const size_t g0 = (size_t)blockIdx.x * blockDim.x + threadIdx.x;
    for (size_t i = g0; i < (size_t)M_ROWS * D_DIM / 4; i += stride) {
        float4 v = reinterpret_cast<const float4*>(x)[i];
        __half2 h0 = __floats2half2_rn(v.x, v.y);
        __half2 h1 = __floats2half2_rn(v.z, v.w);
        reinterpret_cast<uint2*>(g_xh)[i] =
            make_uint2(*(uint32_t*)&h0, *(uint32_t*)&h1);
    }
    // AfT[i][j] = lora_A[d][r][i], j = d*32 + r   (coalesced read, strided write)
    for (size_t idx = g0; idx < (size_t)D_DIM * R_DIM; idx += stride) {
        int j = (int)(idx >> 11);          // 0..127  (idx / 2048)
        int i = (int)(idx & 2047) | ((int)(idx >> 18) << 11);
        // simpler exact mapping: idx = j*D + i
        j = (int)(idx / D_DIM); i = (int)(idx % D_DIM);
        g_AfT[(size_t)i * R_DIM + j] = __float2half_rn(lA[idx]);
    }
    // Bp[n][j] = lora_B[d][n][r], j = d*32 + r
    for (size_t idx = g0; idx < (size_t)D_DIM * R_DIM; idx += stride) {
        int n = (int)(idx >> 7), j = (int)(idx & 127);
        int d = j >> 5, r = j & 31;
        g_Bph[idx] = __float2half_rn(lB[(size_t)(d * D_DIM + n) * 32 + r]);
    }
}

// ---------------- fp16 GEMM (single K source), fp32 accum -------------------
// C[m][n] = bias[n] + Madd[m][n] + sum_K A1[m,k]*B1[n,k]
// CTA 128x128, 8 warps (2M x 4N), warp tile 64x32, BK=64, 3-stage cp.async,
// ldmatrix fragment loads, 2 CTAs/SM.
template<bool OUTH, bool ADDM>
__global__ void __launch_bounds__(256, 2)
gemm_f16(const __half* __restrict__ A1, int lda,
         const __half* __restrict__ B1, int ldb, int K,
         const float* __restrict__ bias, const float* __restrict__ Madd,
         void* __restrict__ Cout, int ldc)
{
    extern __shared__ __align__(16) char smem[];
    const uint32_t sbase = smem_u32(smem);
    const int tid  = threadIdx.x;
    const int wid  = tid >> 5, lane = tid & 31;
    const int g    = lane >> 2, t = lane & 3;
    const int wm   = (wid & 1) * 64, wn = (wid >> 1) * 32;
    const int mBase = blockIdx.y * BM, nBase = blockIdx.x * BN;
    const int NT = K / BK;
    const int lrow = tid >> 1;                 // loader: 2 threads/row
    const int lcol = (tid & 1) * 4;            // 4 chunks of 16B each

    // ldmatrix per-lane base offsets (halves)
    const uint32_t aRow = (uint32_t)(lane & 15);
    const uint32_t aKof = (uint32_t)((lane >> 4) << 3);
    const uint32_t bRow = (uint32_t)(((lane >> 4) << 3) + (lane & 7));
    const uint32_t bKof = (uint32_t)(((lane >> 3) & 1) << 3);

    float acc[4][4][4];
    #pragma unroll
    for (int mi = 0; mi < 4; ++mi)
        #pragma unroll
        for (int ni = 0; ni < 4; ++ni)
            #pragma unroll
            for (int c = 0; c < 4; ++c) acc[mi][ni][c] = 0.f;

    auto load_tile = [&](int kt) {
        if (kt < NT) {
            const int kOff = kt * BK;
            const uint32_t st = sbase + (uint32_t)((kt % STAGES) * STAGE_B);
            const uint32_t so = (uint32_t)(lrow * ROW_B + lcol * 16);
            const __half* ga = A1 + (size_t)(mBase + lrow) * lda + kOff + lcol * 8;
            const __half* gb = B1 + (size_t)(nBase + lrow) * ldb + kOff + lcol * 8;
            #pragma unroll
            for (int c = 0; c < 4; ++c) {
                cp16(st + so + c * 16,         ga + c * 8);
                cp16(st + PLANE + so + c * 16, gb + c * 8);
            }
        }
        asm volatile("cp.async.commit_group;\n" ::: "memory");
    };

    for (int s = 0; s < STAGES - 1; ++s) load_tile(s);

    for (int kt = 0; kt < NT; ++kt) {
        asm volatile("cp.async.wait_group %0;\n" :: "n"(STAGES - 2) : "memory");
        __syncthreads();
        load_tile(kt + STAGES - 1);

        const uint32_t stA = sbase + (uint32_t)((kt % STAGES) * STAGE_B);
        const uint32_t stB = stA + (uint32_t)PLANE;

        #pragma unroll
        for (int k16 = 0; k16 < BK; k16 += 16) {
            uint32_t a[4][4], b[4][2];
            #pragma unroll
            for (int mi = 0; mi < 4; ++mi) {
                const uint32_t addr = stA +
                    ((uint32_t)(wm + mi * 16) + aRow) * ROW_B +
                    ((uint32_t)k16 + aKof) * 2;
                ldsm4(a[mi][0], a[mi][1], a[mi][2], a[mi][3], addr);
            }
            #pragma unroll
            for (int np = 0; np < 2; ++np) {
                const uint32_t addr = stB +
                    ((uint32_t)(wn + np * 16) + bRow) * ROW_B +
                    ((uint32_t)k16 + bKof) * 2;
                ldsm4(b[2 * np][0], b[2 * np][1],
                      b[2 * np + 1][0], b[2 * np + 1][1], addr);
            }
            #pragma unroll
            for (int mi = 0; mi < 4; ++mi)
                #pragma unroll
                for (int ni = 0; ni < 4; ++ni)
                    mma16816(acc[mi][ni],
                             a[mi][0], a[mi][1], a[mi][2], a[mi][3],
                             b[ni][0], b[ni][1]);
        }
    }

    // -------- epilogue -------------------------------------------------------
    #pragma unroll
    for (int mi = 0; mi < 4; ++mi) {
        const int m0 = mBase + wm + mi * 16 + g;
        #pragma unroll
        for (int ni = 0; ni < 4; ++ni) {
            const int n0 = nBase + wn + ni * 8 + 2 * t;
            float v0x = acc[mi][ni][0], v0y = acc[mi][ni][1];
            float v1x = acc[mi][ni][2], v1y = acc[mi][ni][3];
            if (bias) {
                const float2 bv = *reinterpret_cast<const float2*>(bias + n0);
                v0x += bv.x; v0y += bv.y; v1x += bv.x; v1y += bv.y;
            }
            if (ADDM) {
                const float2 w0 =
                    *reinterpret_cast<const float2*>(Madd + (size_t)m0 * ldc + n0);
                const float2 w1 =
                    *reinterpret_cast<const float2*>(Madd + (size_t)(m0 + 8) * ldc + n0);
                v0x += w0.x; v0y += w0.y; v1x += w1.x; v1y += w1.y;
            }
            if (OUTH) {
                __half* C = (__half*)Cout;
                *reinterpret_cast<__half2*>(C + (size_t)m0 * ldc + n0) =
                    __floats2half2_rn(v0x, v0y);
                *reinterpret_cast<__half2*>(C + (size_t)(m0 + 8) * ldc + n0) =
                    __floats2half2_rn(v1x, v1y);
            } else {
                float* C = (float*)Cout;
                *reinterpret_cast<float2*>(C + (size_t)m0 * ldc + n0) =
                    make_float2(v0x, v0y);
                *reinterpret_cast<float2*>(C + (size_t)(m0 + 8) * ldc + n0) =
                    make_float2(v1x, v1y);
            }
        }
    }
}

// ---------------- launch -----------------------------------------------------
extern "C" void kernel_launch(void* const* d_in, const int* in_sizes, int n_in,
                              void* d_out, int out_size) {
    const float* x  = (const float*)d_in[0];   // [4,4096,3072]
    const float* W  = (const float*)d_in[1];   // [3072,3072]
    const float* b  = (const float*)d_in[2];   // [3072]
    const float* lA = (const float*)d_in[3];   // [4,32,3072]
    const float* lB = (const float*)d_in[4];   // [4,3072,32]
    float* out = (float*)d_out;                // [4,4096,3072]

    void *xh, *Wph, *AfT, *Bph;
    cudaGetSymbolAddress(&xh,  g_xh);
    cudaGetSymbolAddress(&Wph, g_Wph);
    cudaGetSymbolAddress(&AfT, g_AfT);
    cudaGetSymbolAddress(&Bph, g_Bph);

    cudaFuncSetAttribute((const void*)gemm_f16<false, false>,
                         cudaFuncAttributeMaxDynamicSharedMemorySize, SMEM_B);
    cudaFuncSetAttribute((const void*)gemm_f16<true, true>,
                         cudaFuncAttributeMaxDynamicSharedMemorySize, SMEM_B);

    // 1) fp16 conversions + packs (x, A^T, Bp); W stays fp32 for the fold
    prep_kernel<<<4096, 256>>>(x, lA, lB);

    // 2) W' = W + Bp @ Aflat   (M=3072, N=3072, K=128) -> fp16 W'
    gemm_f16<true, true><<<dim3(D_DIM / BN, D_DIM / BM), 256, SMEM_B>>>(
        (const __half*)Bph, R_DIM, (const __half*)AfT, R_DIM, R_DIM,
        nullptr, W, Wph, D_DIM);

    // 3) out = x @ W'^T + b   (M=16384, N=3072, K=3072)
    gemm_f16<false, false><<<dim3(D_DIM / BN, M_ROWS / BM), 256, SMEM_B>>>(
        (const __half*)xh, D_DIM, (const __half*)Wph, D_DIM, D_DIM,
        b, nullptr, out, D_DIM);
}